// round 2
// baseline (speedup 1.0000x reference)
#include <cuda_runtime.h>
#include <math.h>
#include <stdint.h>

// ----------------------------------------------------------------------------
// Problem constants
// ----------------------------------------------------------------------------
#define WAY   100
#define SHOT  5
#define DIM   2048
#define NQ    10000
#define KSEL  512

// ----------------------------------------------------------------------------
// Static device scratch (no allocations allowed)
// ----------------------------------------------------------------------------
// float buffer layout (offsets in floats)
#define O_P0R   0                       // 100*2048
#define O_P0D   (O_P0R + WAY*DIM)
#define O_P1    (O_P0D + WAY*DIM)
#define O_QNR   (O_P1  + WAY*DIM)       // 10000
#define O_QND   (O_QNR + NQ)
#define O_GR    (O_QND + NQ)            // 10000*100
#define O_GD    (O_GR  + NQ*WAY)
#define O_G2    (O_GD  + NQ*WAY)
#define O_LH    (O_G2  + NQ*WAY)
#define O_LL    (O_LH  + NQ*WAY)
#define O_CERT  (O_LL  + NQ*WAY)        // 10000
#define O_SELV  (O_CERT + NQ)           // 512
#define O_ABSR  (O_SELV + KSEL)
#define O_ABSD  (O_ABSR + NQ)
#define O_RELR  (O_ABSD + NQ)
#define O_RELD  (O_RELR + NQ)
#define O_CN1   (O_RELD + NQ)           // 100 each
#define O_SC1   (O_CN1 + WAY)
#define O_CN2   (O_SC1 + WAY)
#define O_SC2   (O_CN2 + WAY)
#define O_SCH   (O_SC2 + WAY)
#define O_SCL   (O_SCH + WAY)
#define O_KL    (O_SCL + WAY)
#define BUF_FLOATS (O_KL + WAY)

__device__ float g_buf[BUF_FLOATS];

// int buffer layout
#define IO_RES   0         // 10000
#define IO_DCT   10000     // 10000
#define IO_SELI  20000     // 512
#define IO_PSE   20512     // 512
#define IO_SELK  21024     // 1
#define IO_CNTS  21025     // 2 : R, D
#define IBUF_INTS 21027

__device__ int g_ibuf[IBUF_INTS];
__device__ int g_fullCnt = NQ;

// ----------------------------------------------------------------------------
// Block reduction helpers (blockDim == 256, deterministic fixed tree)
// ----------------------------------------------------------------------------
__device__ __forceinline__ float blockReduceSum256(float v, float* s) {
    int t = threadIdx.x;
    __syncthreads();
    s[t] = v; __syncthreads();
    #pragma unroll
    for (int o = 128; o > 0; o >>= 1) {
        if (t < o) s[t] += s[t + o];
        __syncthreads();
    }
    float r = s[0];
    __syncthreads();
    return r;
}

__device__ __forceinline__ float blockReduceMax256(float v, float* s) {
    int t = threadIdx.x;
    __syncthreads();
    s[t] = v; __syncthreads();
    #pragma unroll
    for (int o = 128; o > 0; o >>= 1) {
        if (t < o) s[t] = fmaxf(s[t], s[t + o]);
        __syncthreads();
    }
    float r = s[0];
    __syncthreads();
    return r;
}

// Exclusive scan of 0/1 flags over 1024 threads (stable, deterministic).
// ws must have >= 32 ints. Returns exclusive prefix; *tot gets the total.
__device__ __forceinline__ int blockScan1024(int v, int* tot, int* ws) {
    int t = threadIdx.x;
    int lane = t & 31, w = t >> 5;
    int x = v;
    #pragma unroll
    for (int o = 1; o < 32; o <<= 1) {
        int y = __shfl_up_sync(0xffffffffu, x, o);
        if (lane >= o) x += y;
    }
    if (lane == 31) ws[w] = x;
    __syncthreads();
    if (w == 0) {
        int s2 = ws[lane];
        #pragma unroll
        for (int o = 1; o < 32; o <<= 1) {
            int y = __shfl_up_sync(0xffffffffu, s2, o);
            if (lane >= o) s2 += y;
        }
        ws[lane] = s2;
    }
    __syncthreads();
    int base = (w > 0) ? ws[w - 1] : 0;
    int excl = base + x - v;
    *tot = ws[31];
    __syncthreads();
    return excl;
}

__device__ __forceinline__ unsigned orderedKey(float f) {
    unsigned u = __float_as_uint(f);
    return (u & 0x80000000u) ? ~u : (u | 0x80000000u);
}

// ----------------------------------------------------------------------------
// K1: proto0[c,:] = l2norm(mean over shots)
// ----------------------------------------------------------------------------
__global__ void k_proto0(const float* __restrict__ shot, float* __restrict__ proto) {
    int c = blockIdx.x;
    __shared__ float red[256];
    float ssq = 0.f;
    for (int d = threadIdx.x; d < DIM; d += 256) {
        float m = 0.f;
        #pragma unroll
        for (int s = 0; s < SHOT; s++) m += shot[((size_t)c * SHOT + s) * DIM + d];
        m = m / (float)SHOT;
        proto[(size_t)c * DIM + d] = m;
        ssq += m * m;
    }
    float tot = blockReduceSum256(ssq, red);
    __shared__ float inv;
    if (threadIdx.x == 0) inv = 1.0f / fmaxf(sqrtf(tot), 1e-12f);
    __syncthreads();
    for (int d = threadIdx.x; d < DIM; d += 256)
        proto[(size_t)c * DIM + d] *= inv;
}

// ----------------------------------------------------------------------------
// K2: per-row query norm (clamped)
// ----------------------------------------------------------------------------
__global__ void k_qnorm(const float* __restrict__ X, float* __restrict__ qn) {
    int q = blockIdx.x;
    __shared__ float red[256];
    const float* row = X + (size_t)q * DIM;
    float ssq = 0.f;
    for (int d = threadIdx.x; d < DIM; d += 256) { float v = row[d]; ssq += v * v; }
    float tot = blockReduceSum256(ssq, red);
    if (threadIdx.x == 0) qn[q] = fmaxf(sqrtf(tot), 1e-12f);
}

// ----------------------------------------------------------------------------
// K3: GEMM  C[j,c] = dot(A[row_j,:], P[c,:]) / qn[row_j]
//     row_j = map ? map[j] : j ; j < *cnt ; ldc = 100
// ----------------------------------------------------------------------------
#define G_TQ 64
#define G_KC 32
__global__ __launch_bounds__(256) void k_gemm(
    const float* __restrict__ A, const float* __restrict__ qn,
    const float* __restrict__ P, float* __restrict__ C,
    const int* __restrict__ map, const int* __restrict__ cnt)
{
    int Q = *cnt;
    int rowBase = blockIdx.x * G_TQ;
    if (rowBase >= Q) return;

    __shared__ float As[G_TQ][G_KC + 1];
    __shared__ float Bs[112][G_KC + 1];

    int tx = threadIdx.x & 15, ty = threadIdx.x >> 4;  // 16 x 16
    float acc[4][7];
    #pragma unroll
    for (int i = 0; i < 4; i++)
        #pragma unroll
        for (int j = 0; j < 7; j++) acc[i][j] = 0.f;

    for (int k0 = 0; k0 < DIM; k0 += G_KC) {
        // stage A tile (64 x 32)
        #pragma unroll
        for (int t = threadIdx.x; t < G_TQ * G_KC; t += 256) {
            int r = t / G_KC, k = t % G_KC;
            int j = rowBase + r;
            float v = 0.f;
            if (j < Q) {
                int gq = map ? map[j] : j;
                v = A[(size_t)gq * DIM + k0 + k];
            }
            As[r][k] = v;
        }
        // stage B tile (112 x 32, rows >= 100 zeroed)
        for (int t = threadIdx.x; t < 112 * G_KC; t += 256) {
            int c = t / G_KC, k = t % G_KC;
            Bs[c][k] = (c < WAY) ? P[(size_t)c * DIM + k0 + k] : 0.f;
        }
        __syncthreads();
        #pragma unroll
        for (int kk = 0; kk < G_KC; kk++) {
            float a0 = As[ty * 4 + 0][kk];
            float a1 = As[ty * 4 + 1][kk];
            float a2 = As[ty * 4 + 2][kk];
            float a3 = As[ty * 4 + 3][kk];
            #pragma unroll
            for (int jj = 0; jj < 7; jj++) {
                float b = Bs[tx + 16 * jj][kk];
                acc[0][jj] += a0 * b;
                acc[1][jj] += a1 * b;
                acc[2][jj] += a2 * b;
                acc[3][jj] += a3 * b;
            }
        }
        __syncthreads();
    }
    #pragma unroll
    for (int i = 0; i < 4; i++) {
        int j = rowBase + ty * 4 + i;
        if (j < Q) {
            int gq = map ? map[j] : j;
            float inv = 1.0f / qn[gq];
            #pragma unroll
            for (int jj = 0; jj < 7; jj++) {
                int c = tx + 16 * jj;
                if (c < WAY) C[(size_t)j * WAY + c] = acc[i][jj] * inv;
            }
        }
    }
}

// ----------------------------------------------------------------------------
// K4: column L2 norm over (possibly gathered) rows
// ----------------------------------------------------------------------------
__global__ void k_colnorm(const float* __restrict__ C, const int* __restrict__ map,
                          const int* __restrict__ cnt, float* __restrict__ cn)
{
    int c = blockIdx.x;
    int Q = *cnt;
    __shared__ float red[256];
    float ssq = 0.f;
    for (int j = threadIdx.x; j < Q; j += 256) {
        int r = map ? map[j] : j;
        float v = C[(size_t)r * WAY + c];
        ssq += v * v;
    }
    float tot = blockReduceSum256(ssq, red);
    if (threadIdx.x == 0) cn[c] = sqrtf(tot);
}

// scale[c] = tp / (cn[c] + 1e-6)
__global__ void k_scale(const float* __restrict__ cn, const float* __restrict__ tpp,
                        float* __restrict__ sc)
{
    int c = threadIdx.x;
    if (c < WAY) sc[c] = (*tpp) / (cn[c] + 1e-6f);
}

// ----------------------------------------------------------------------------
// K5: cert[j] = max_c C[row_j,c]*scale[c]
// ----------------------------------------------------------------------------
__global__ void k_cert(const float* __restrict__ C, const float* __restrict__ sc,
                       const int* __restrict__ map, const int* __restrict__ cnt,
                       float* __restrict__ cert)
{
    int j = blockIdx.x * blockDim.x + threadIdx.x;
    int Q = *cnt;
    if (j >= Q) return;
    int r = map ? map[j] : j;
    const float* row = C + (size_t)r * WAY;
    float best = -3.4e38f;
    #pragma unroll 4
    for (int c = 0; c < WAY; c++) {
        float v = row[c] * sc[c];
        if (v > best) best = v;
    }
    cert[j] = best;
}

// ----------------------------------------------------------------------------
// K6: single-block radix top-k (k = min(Q,512)), stable by index.
// ----------------------------------------------------------------------------
__global__ __launch_bounds__(1024) void k_topk(
    const float* __restrict__ cert, const int* __restrict__ cnt,
    int* __restrict__ selIdx, float* __restrict__ selVal, int* __restrict__ selK)
{
    const int T = 1024;
    int t = threadIdx.x;
    __shared__ unsigned hist[2048];
    __shared__ int ws[32];
    __shared__ unsigned shPrefix, shMask;
    __shared__ int shRem;
    int Q = *cnt;
    int k = (Q < KSEL) ? Q : KSEL;
    if (t == 0) { shPrefix = 0u; shMask = 0u; shRem = k; }
    __syncthreads();

    for (int pass = 0; pass < 3; pass++) {
        int shift = (pass == 0) ? 21 : ((pass == 1) ? 10 : 0);
        int nb = (pass == 2) ? 1024 : 2048;
        for (int i = t; i < 2048; i += T) hist[i] = 0u;
        __syncthreads();
        unsigned pfx = shPrefix, msk = shMask;
        for (int j = t; j < Q; j += T) {
            unsigned u = orderedKey(cert[j]);
            if ((u & msk) == pfx) atomicAdd(&hist[(u >> shift) & (nb - 1)], 1u);
        }
        __syncthreads();
        if (t == 0) {
            int rem = shRem;
            unsigned acc = 0;
            int b;
            for (b = nb - 1; b >= 0; b--) {
                unsigned h = hist[b];
                if (acc + h >= (unsigned)rem) break;
                acc += h;
            }
            if (b < 0) b = 0;
            shPrefix = pfx | ((unsigned)b << shift);
            shMask = msk | ((unsigned)(nb - 1) << shift);
            shRem = rem - (int)acc;
        }
        __syncthreads();
    }
    unsigned Kkey = shPrefix;
    int rem = shRem;

    __shared__ int eqBase, selBase;
    if (t == 0) { eqBase = 0; selBase = 0; }
    __syncthreads();
    for (int j0 = 0; j0 < Q; j0 += T) {
        int j = j0 + t;
        int isGt = 0, isEq = 0;
        float v = 0.f;
        if (j < Q) {
            v = cert[j];
            unsigned u = orderedKey(v);
            isGt = (u > Kkey);
            isEq = (u == Kkey);
        }
        int eqTot;
        int eqEx = blockScan1024(isEq, &eqTot, ws);
        int sel = isGt | (isEq & ((eqBase + eqEx) < rem));
        int sTot;
        int sEx = blockScan1024(sel, &sTot, ws);
        if (sel) {
            int slot = selBase + sEx;
            selIdx[slot] = j;
            selVal[slot] = v;
        }
        __syncthreads();
        if (t == 0) { eqBase += eqTot; selBase += sTot; }
        __syncthreads();
    }
    if (t == 0) *selK = k;
}

// ----------------------------------------------------------------------------
// K7: pseudo labels (argmax over classes of scaled logits row)
// ----------------------------------------------------------------------------
__global__ void k_pseudo(const float* __restrict__ C, const float* __restrict__ sc,
                         const int* __restrict__ map, const int* __restrict__ selIdx,
                         const int* __restrict__ selK, int* __restrict__ pseudo)
{
    int i = blockIdx.x * blockDim.x + threadIdx.x;
    if (i >= *selK) return;
    int j = selIdx[i];
    int r = map ? map[j] : j;
    const float* row = C + (size_t)r * WAY;
    float best = -3.4e38f;
    int bc = 0;
    for (int c = 0; c < WAY; c++) {
        float v = row[c] * sc[c];
        if (v > best) { best = v; bc = c; }
    }
    pseudo[i] = bc;
}

// ----------------------------------------------------------------------------
// K8: refined proto: P1[c,:] = P0[c,:] + sum_{i: pseudo_i==c} val_i/(K*qn) * A[q_i,:]
// ----------------------------------------------------------------------------
__global__ void k_proto1(const float* __restrict__ P0, const float* __restrict__ A,
                         const float* __restrict__ qn, const int* __restrict__ map,
                         const int* __restrict__ selIdx, const float* __restrict__ selVal,
                         const int* __restrict__ selK, const int* __restrict__ pseudo,
                         float* __restrict__ P1)
{
    int c = blockIdx.x;
    __shared__ int sPse[KSEL];
    __shared__ int sQ[KSEL];
    __shared__ float sCoef[KSEL];
    int K = *selK;
    for (int i = threadIdx.x; i < K; i += 256) {
        int j = selIdx[i];
        int gq = map ? map[j] : j;
        sPse[i] = pseudo[i];
        sQ[i] = gq;
        sCoef[i] = selVal[i] / ((float)K * qn[gq]);
    }
    __syncthreads();
    for (int d = threadIdx.x; d < DIM; d += 256) {
        float acc = P0[(size_t)c * DIM + d];
        for (int i = 0; i < K; i++)
            if (sPse[i] == c) acc += sCoef[i] * A[(size_t)sQ[i] * DIM + d];
        P1[(size_t)c * DIM + d] = acc;
    }
}

// ----------------------------------------------------------------------------
// K9: per-row softmax stats (abs_c = row max, rel_c = sum p*log(p+1e-10))
// ----------------------------------------------------------------------------
__global__ void k_rowstats(const float* __restrict__ C, const float* __restrict__ sc,
                           const int* __restrict__ cnt,
                           float* __restrict__ absc, float* __restrict__ relc)
{
    int warp = (blockIdx.x * blockDim.x + threadIdx.x) >> 5;
    int lane = threadIdx.x & 31;
    if (warp >= *cnt) return;
    const float* row = C + (size_t)warp * WAY;
    float m = -3.4e38f;
    for (int c = lane; c < WAY; c += 32) m = fmaxf(m, row[c] * sc[c]);
    #pragma unroll
    for (int o = 16; o > 0; o >>= 1) m = fmaxf(m, __shfl_xor_sync(0xffffffffu, m, o));
    float Z = 0.f;
    for (int c = lane; c < WAY; c += 32) Z += expf(row[c] * sc[c] - m);
    #pragma unroll
    for (int o = 16; o > 0; o >>= 1) Z += __shfl_xor_sync(0xffffffffu, Z, o);
    float rel = 0.f;
    for (int c = lane; c < WAY; c += 32) {
        float p = expf(row[c] * sc[c] - m) / Z;
        rel += p * logf(p + 1e-10f);
    }
    #pragma unroll
    for (int o = 16; o > 0; o >>= 1) rel += __shfl_xor_sync(0xffffffffu, rel, o);
    if (lane == 0) { absc[warp] = m; relc[warp] = rel; }
}

// ----------------------------------------------------------------------------
// K10: partition by diff sign, stable order; writes index lists + out floats
// ----------------------------------------------------------------------------
__global__ __launch_bounds__(1024) void k_partition(
    const float* __restrict__ ar, const float* __restrict__ ad,
    const float* __restrict__ rr, const float* __restrict__ rd,
    int* __restrict__ resIdx, int* __restrict__ dctIdx,
    int* __restrict__ cnts, float* __restrict__ out)
{
    const int T = 1024;
    int t = threadIdx.x;
    __shared__ int ws[32];
    __shared__ int runBase;
    __shared__ int Rsh;
    if (t == 0) runBase = 0;
    __syncthreads();
    // pass 1: diff > 0 -> res
    for (int j0 = 0; j0 < NQ; j0 += T) {
        int j = j0 + t;
        int f = 0;
        if (j < NQ) {
            float diff = ar[j] - ad[j] + rr[j] - rd[j];
            f = (diff > 0.f);
        }
        int tot;
        int ex = blockScan1024(f, &tot, ws);
        if (f) {
            int slot = runBase + ex;
            resIdx[slot] = j;
            out[2 + slot] = (float)j;
        }
        __syncthreads();
        if (t == 0) runBase += tot;
        __syncthreads();
    }
    if (t == 0) { Rsh = runBase; cnts[0] = runBase; runBase = 0; }
    __syncthreads();
    int R = Rsh;
    // pass 2: diff < 0 -> dct
    for (int j0 = 0; j0 < NQ; j0 += T) {
        int j = j0 + t;
        int f = 0;
        if (j < NQ) {
            float diff = ar[j] - ad[j] + rr[j] - rd[j];
            f = (diff < 0.f);
        }
        int tot;
        int ex = blockScan1024(f, &tot, ws);
        if (f) {
            int slot = runBase + ex;
            dctIdx[slot] = j;
            out[2 + R + slot] = (float)j;
        }
        __syncthreads();
        if (t == 0) runBase += tot;
        __syncthreads();
    }
    if (t == 0) cnts[1] = runBase;
}

// ----------------------------------------------------------------------------
// K11: confidence weights
// ----------------------------------------------------------------------------
__global__ void k_w(const float* __restrict__ ar, const float* __restrict__ ad,
                    const int* __restrict__ cnts, float* __restrict__ out)
{
    int q = blockIdx.x * blockDim.x + threadIdx.x;
    if (q >= NQ) return;
    int base = 2 + cnts[0] + cnts[1];
    float a = ar[q], b = ad[q];
    float den = fmaxf(a + b, 1e-8f);
    out[base + q] = a / den;
    out[base + NQ + q] = b / den;
}

// ----------------------------------------------------------------------------
// K12: per-class KL sum over the query dim (softmax over queries per class)
// ----------------------------------------------------------------------------
__global__ void k_classkl(const float* __restrict__ Lh, const float* __restrict__ sch,
                          const float* __restrict__ Ll, const float* __restrict__ scl,
                          const int* __restrict__ cnt, float* __restrict__ kl)
{
    int c = blockIdx.x;
    int Q = *cnt;
    float sh = sch[c], sl = scl[c];
    __shared__ float red[256];
    float mh = -3.4e38f, ml = -3.4e38f;
    for (int j = threadIdx.x; j < Q; j += 256) {
        mh = fmaxf(mh, Lh[(size_t)j * WAY + c] * sh);
        ml = fmaxf(ml, Ll[(size_t)j * WAY + c] * sl);
    }
    mh = blockReduceMax256(mh, red);
    ml = blockReduceMax256(ml, red);
    float Zh = 0.f, Zl = 0.f;
    for (int j = threadIdx.x; j < Q; j += 256) {
        Zh += expf(Lh[(size_t)j * WAY + c] * sh - mh);
        Zl += expf(Ll[(size_t)j * WAY + c] * sl - ml);
    }
    Zh = blockReduceSum256(Zh, red);
    Zl = blockReduceSum256(Zl, red);
    float lZl = logf(Zl);
    float s = 0.f;
    for (int j = threadIdx.x; j < Q; j += 256) {
        float lh = Lh[(size_t)j * WAY + c] * sh;
        float ll = Ll[(size_t)j * WAY + c] * sl;
        float p = expf(lh - mh) / Zh;
        s += p * (logf(p) - (ll - ml - lZl));
    }
    s = blockReduceSum256(s, red);
    if (threadIdx.x == 0) kl[c] = s;
}

// ----------------------------------------------------------------------------
// K13: finalize loss = w0 * sum(kl) / (sum_w + 1e-8) * tempScalar
// ----------------------------------------------------------------------------
__global__ void k_finalize(const float* __restrict__ kl, const float* __restrict__ absc,
                           const int* __restrict__ subsetIdx, const int* __restrict__ cnt,
                           const float* __restrict__ tempScalar, float* __restrict__ outSlot)
{
    __shared__ float red[256];
    int Q = *cnt;
    float s = 0.f;
    for (int c = threadIdx.x; c < WAY; c += 256) s += kl[c];
    s = blockReduceSum256(s, red);
    float sw = 0.f;
    for (int j = threadIdx.x; j < Q; j += 256) sw += absc[subsetIdx[j]];
    sw = blockReduceSum256(sw, red);
    if (threadIdx.x == 0) {
        float w0 = (Q > 0) ? absc[subsetIdx[0]] : 0.f;
        float loss = w0 * s / (sw + 1e-8f);
        *outSlot = (*tempScalar) * loss;
    }
}

// ----------------------------------------------------------------------------
// Host-side orchestration
// ----------------------------------------------------------------------------
struct Ptrs {
    float *P0R, *P0D, *P1, *QNR, *QND, *GR, *GD, *G2, *LH, *LL;
    float *CERT, *SELV, *ABSR, *ABSD, *RELR, *RELD;
    float *CN1, *SC1, *CN2, *SC2, *SCH, *SCL, *KL;
    int *RES, *DCT, *SELI, *PSE, *SELK, *CNTS;
    int *FULLCNT;
    const float *tp;
};

// run the "distance tail": from a precomputed proto0-GEMM G + map/cnt
// to final (raw logits2 in Lout, scale in scOut)
static void distance_tail(const Ptrs& p,
                          const float* A, const float* qn, const float* P0,
                          const float* G, const int* map, const int* cnt,
                          float* Lout, float* scOut)
{
    k_colnorm<<<WAY, 256>>>(G, map, cnt, p.CN1);
    k_scale<<<1, 128>>>(p.CN1, p.tp, p.SC1);
    k_cert<<<(NQ + 255) / 256, 256>>>(G, p.SC1, map, cnt, p.CERT);
    k_topk<<<1, 1024>>>(p.CERT, cnt, p.SELI, p.SELV, p.SELK);
    k_pseudo<<<2, 256>>>(G, p.SC1, map, p.SELI, p.SELK, p.PSE);
    k_proto1<<<WAY, 256>>>(P0, A, qn, map, p.SELI, p.SELV, p.SELK, p.PSE, p.P1);
    k_gemm<<<(NQ + G_TQ - 1) / G_TQ, 256>>>(A, qn, p.P1, Lout, map, cnt);
    k_colnorm<<<WAY, 256>>>(Lout, nullptr, cnt, p.CN2);
    k_scale<<<1, 128>>>(p.CN2, p.tp, scOut);
}

extern "C" void kernel_launch(void* const* d_in, const int* in_sizes, int n_in,
                              void* d_out, int out_size)
{
    const float* x_shot    = (const float*)d_in[0];
    const float* x_query   = (const float*)d_in[1];
    const float* dct_shot  = (const float*)d_in[2];
    const float* dct_query = (const float*)d_in[3];
    const float* tp        = (const float*)d_in[4];
    const float* temp      = (const float*)d_in[5];
    const float* temp_dct  = (const float*)d_in[6];
    float* out = (float*)d_out;

    float* B = nullptr;
    int* IB = nullptr;
    int* FC = nullptr;
    cudaGetSymbolAddress((void**)&B, g_buf);
    cudaGetSymbolAddress((void**)&IB, g_ibuf);
    cudaGetSymbolAddress((void**)&FC, g_fullCnt);

    Ptrs p;
    p.P0R = B + O_P0R; p.P0D = B + O_P0D; p.P1 = B + O_P1;
    p.QNR = B + O_QNR; p.QND = B + O_QND;
    p.GR = B + O_GR; p.GD = B + O_GD; p.G2 = B + O_G2;
    p.LH = B + O_LH; p.LL = B + O_LL;
    p.CERT = B + O_CERT; p.SELV = B + O_SELV;
    p.ABSR = B + O_ABSR; p.ABSD = B + O_ABSD;
    p.RELR = B + O_RELR; p.RELD = B + O_RELD;
    p.CN1 = B + O_CN1; p.SC1 = B + O_SC1; p.CN2 = B + O_CN2; p.SC2 = B + O_SC2;
    p.SCH = B + O_SCH; p.SCL = B + O_SCL; p.KL = B + O_KL;
    p.RES = IB + IO_RES; p.DCT = IB + IO_DCT; p.SELI = IB + IO_SELI;
    p.PSE = IB + IO_PSE; p.SELK = IB + IO_SELK; p.CNTS = IB + IO_CNTS;
    p.FULLCNT = FC;
    p.tp = tp;

    const int GEMM_GRID = (NQ + G_TQ - 1) / G_TQ;

    // ---- full pipeline, stream r ----
    k_proto0<<<WAY, 256>>>(x_shot, p.P0R);
    k_qnorm<<<NQ, 256>>>(x_query, p.QNR);
    k_gemm<<<GEMM_GRID, 256>>>(x_query, p.QNR, p.P0R, p.GR, nullptr, p.FULLCNT);
    distance_tail(p, x_query, p.QNR, p.P0R, p.GR, nullptr, p.FULLCNT, p.G2, p.SC2);
    k_rowstats<<<(NQ * 32 + 255) / 256, 256>>>(p.G2, p.SC2, p.FULLCNT, p.ABSR, p.RELR);

    // ---- full pipeline, stream d ----
    k_proto0<<<WAY, 256>>>(dct_shot, p.P0D);
    k_qnorm<<<NQ, 256>>>(dct_query, p.QND);
    k_gemm<<<GEMM_GRID, 256>>>(dct_query, p.QND, p.P0D, p.GD, nullptr, p.FULLCNT);
    distance_tail(p, dct_query, p.QND, p.P0D, p.GD, nullptr, p.FULLCNT, p.G2, p.SC2);
    k_rowstats<<<(NQ * 32 + 255) / 256, 256>>>(p.G2, p.SC2, p.FULLCNT, p.ABSD, p.RELD);

    // ---- partition + weights ----
    k_partition<<<1, 1024>>>(p.ABSR, p.ABSD, p.RELR, p.RELD, p.RES, p.DCT, p.CNTS, out);
    k_w<<<(NQ + 255) / 256, 256>>>(p.ABSR, p.ABSD, p.CNTS, out);

    const int* CR = p.CNTS + 0;  // R
    const int* CD = p.CNTS + 1;  // D

    // ---- loss_dctl: lrh (x on res, high), ldl (dct on res, low), weight abs_c[res] ----
    distance_tail(p, x_query, p.QNR, p.P0R, p.GR, p.RES, CR, p.LH, p.SCH);
    distance_tail(p, dct_query, p.QND, p.P0D, p.GD, p.RES, CR, p.LL, p.SCL);
    k_classkl<<<WAY, 256>>>(p.LH, p.SCH, p.LL, p.SCL, CR, p.KL);
    k_finalize<<<1, 256>>>(p.KL, p.ABSR, p.RES, CR, temp_dct, out + 1);

    // ---- loss_resl: ldh (dct on dct, high), lrl (x on dct, low), weight abs_cd[dct] ----
    distance_tail(p, dct_query, p.QND, p.P0D, p.GD, p.DCT, CD, p.LH, p.SCH);
    distance_tail(p, x_query, p.QNR, p.P0R, p.GR, p.DCT, CD, p.LL, p.SCL);
    k_classkl<<<WAY, 256>>>(p.LH, p.SCH, p.LL, p.SCL, CD, p.KL);
    k_finalize<<<1, 256>>>(p.KL, p.ABSD, p.DCT, CD, temp, out + 0);
}

// round 3
// speedup vs baseline: 2.5376x; 2.5376x over previous
#include <cuda_runtime.h>
#include <math.h>
#include <stdint.h>

#define WAY   100
#define SHOT  5
#define DIM   2048
#define NQ    10000
#define KSEL  512
#define TQ    64
#define TKC   32
#define NT    157          // ceil(NQ/TQ)
#define BSS   113          // Bs row stride (conflict-free transpose staging)

// ---------------- static scratch ----------------
#define SLP (WAY*DIM)
#define O_P0   0
#define O_P1   (O_P0 + 2*SLP)
#define O_QN   (O_P1 + 4*SLP)
#define O_G    (O_QN + 2*NQ)
#define O_L    (O_G  + 2*NQ*WAY)
#define O_CERT (O_L  + 4*NQ*WAY)
#define O_SELV (O_CERT + 4*NQ)
#define O_STAT (O_SELV + 4*KSEL)
#define O_SC1  (O_STAT + 4*NQ)
#define O_SC2  (O_SC1 + 4*WAY)
#define O_KL   (O_SC2 + 4*WAY)
#define O_PART (O_KL + 2*WAY)
#define TOTF   (O_PART + 4*NT*112)
__device__ float g_buf[TOTF];

#define IO_RES  0
#define IO_DCT  NQ
#define IO_SELI (2*NQ)
#define IO_PSE  (2*NQ+4*KSEL)
#define IO_SELK (2*NQ+8*KSEL)
#define IO_CNTS (2*NQ+8*KSEL+4)
__device__ int g_ibuf[2*NQ+8*KSEL+8];
__device__ int g_fullCnt = NQ;

// ---------------- job structs ----------------
struct GJob { const float* A; const float* qn; const float* P; float* C;
              float* part; const int* map; const int* cnt; };
struct GJobs { GJob j[4]; };
struct JSet {
    const float* A[4]; const float* qn[4]; const float* P0[4]; const float* G[4];
    const int* map[4]; const int* cnt[4];
    float* P1[4]; float* cert[4]; float* selv[4]; float* sc1[4]; float* sc2[4];
    int* seli[4]; int* selk[4]; int* pse[4];
    const float* part[4];
};
struct RSJ { const float* L[2]; const float* sc[2]; float* absc[2]; float* relc[2]; };
struct KLJ { const float* Lh[2]; const float* sch[2]; const float* Ll[2];
             const float* scl[2]; const int* cnt[2]; float* kl[2]; };
struct FinJ { const float* kl[2]; const float* absc[2]; const int* idx[2];
              const int* cnt[2]; const float* tsc[2]; float* slot[2]; };

// ---------------- reductions ----------------
__device__ __forceinline__ float bSum256(float v, float* s) {
    int t = threadIdx.x; __syncthreads(); s[t] = v; __syncthreads();
    #pragma unroll
    for (int o = 128; o > 0; o >>= 1) { if (t < o) s[t] += s[t+o]; __syncthreads(); }
    float r = s[0]; __syncthreads(); return r;
}
__device__ __forceinline__ float bMax256(float v, float* s) {
    int t = threadIdx.x; __syncthreads(); s[t] = v; __syncthreads();
    #pragma unroll
    for (int o = 128; o > 0; o >>= 1) { if (t < o) s[t] = fmaxf(s[t], s[t+o]); __syncthreads(); }
    float r = s[0]; __syncthreads(); return r;
}
__device__ __forceinline__ int bScan1024(int v, int* tot, int* ws) {
    int t = threadIdx.x, lane = t & 31, w = t >> 5, x = v;
    #pragma unroll
    for (int o = 1; o < 32; o <<= 1) { int y = __shfl_up_sync(~0u, x, o); if (lane >= o) x += y; }
    if (lane == 31) ws[w] = x;
    __syncthreads();
    if (w == 0) {
        int s2 = ws[lane];
        #pragma unroll
        for (int o = 1; o < 32; o <<= 1) { int y = __shfl_up_sync(~0u, s2, o); if (lane >= o) s2 += y; }
        ws[lane] = s2;
    }
    __syncthreads();
    int r = (w ? ws[w-1] : 0) + x - v; *tot = ws[31]; __syncthreads(); return r;
}
__device__ __forceinline__ unsigned okey(float f) {
    unsigned u = __float_as_uint(f);
    return (u & 0x80000000u) ? ~u : (u | 0x80000000u);
}

// ---------------- proto0 (2 jobs) ----------------
__global__ void k_proto0(const float* __restrict__ s0, const float* __restrict__ s1,
                         float* __restrict__ p0, float* __restrict__ p1) {
    const float* shot = blockIdx.y ? s1 : s0;
    float* proto = blockIdx.y ? p1 : p0;
    int c = blockIdx.x;
    __shared__ float red[256];
    const float4* sB = (const float4*)(shot + (size_t)c*SHOT*DIM);
    float4* pB = (float4*)(proto + (size_t)c*DIM);
    float ssq = 0.f;
    for (int d = threadIdx.x; d < DIM/4; d += 256) {
        float4 a = make_float4(0,0,0,0);
        #pragma unroll
        for (int s = 0; s < SHOT; s++) {
            float4 v = sB[s*(DIM/4)+d];
            a.x += v.x; a.y += v.y; a.z += v.z; a.w += v.w;
        }
        a.x *= 0.2f; a.y *= 0.2f; a.z *= 0.2f; a.w *= 0.2f;
        pB[d] = a;
        ssq += a.x*a.x + a.y*a.y + a.z*a.z + a.w*a.w;
    }
    float tot = bSum256(ssq, red);
    __shared__ float inv;
    if (threadIdx.x == 0) inv = 1.f / fmaxf(sqrtf(tot), 1e-12f);
    __syncthreads();
    for (int d = threadIdx.x; d < DIM/4; d += 256) {
        float4 a = pB[d]; a.x *= inv; a.y *= inv; a.z *= inv; a.w *= inv; pB[d] = a;
    }
}

// ---------------- query norms (2 jobs) ----------------
__global__ void k_qnorm(const float* __restrict__ x0, const float* __restrict__ x1,
                        float* __restrict__ q0, float* __restrict__ q1) {
    const float* X = blockIdx.y ? x1 : x0;
    float* qn = blockIdx.y ? q0 + 0 : q0;  // placeholder fixed below
    qn = blockIdx.y ? q1 : q0;
    __shared__ float red[256];
    const float4* row = (const float4*)(X + (size_t)blockIdx.x*DIM);
    float ssq = 0.f;
    #pragma unroll
    for (int i = 0; i < 2; i++) {
        float4 v = row[threadIdx.x + 256*i];
        ssq += v.x*v.x + v.y*v.y + v.z*v.z + v.w*v.w;
    }
    float tot = bSum256(ssq, red);
    if (threadIdx.x == 0) qn[blockIdx.x] = fmaxf(sqrtf(tot), 1e-12f);
}

// ---------------- GEMM v2 ----------------
__global__ __launch_bounds__(256) void k_gemm(GJobs g) {
    __shared__ float4 As4[TQ][8];
    __shared__ float Bs[TKC][BSS];
    __shared__ float tmp[16][112];
    __shared__ int rowIdx[TQ];
    __shared__ float rowInv[TQ];

    int job = blockIdx.x / NT, tb = blockIdx.x - job*NT;
    GJob J = g.j[job];
    int Q = *J.cnt;
    int rowBase = tb * TQ;
    if (rowBase >= Q) return;

    int t = threadIdx.x, tx = t & 15, ty = t >> 4;

    // zero B pad cols once
    for (int i = t; i < TKC*13; i += 256) Bs[i/13][100 + i%13] = 0.f;
    if (t < TQ) {
        int j = rowBase + t; int gq = 0; float iv = 0.f;
        if (j < Q) { gq = J.map ? J.map[j] : j; iv = 1.f / J.qn[gq]; }
        rowIdx[t] = gq; rowInv[t] = iv;
    }
    __syncthreads();

    int r0 = t >> 3, k4 = t & 7;
    const float4* aP0 = (const float4*)(J.A + (size_t)rowIdx[r0]*DIM) + k4;
    const float4* aP1 = (const float4*)(J.A + (size_t)rowIdx[r0+32]*DIM) + k4;
    int f1 = t, f2 = t+256, f3 = t+512, f4 = t+768;
    const float4* bP1 = (const float4*)(J.P + (size_t)(f1>>3)*DIM) + (f1&7);
    const float4* bP2 = (const float4*)(J.P + (size_t)(f2>>3)*DIM) + (f2&7);
    const float4* bP3 = (const float4*)(J.P + (size_t)(f3>>3)*DIM) + (f3&7);
    const float4* bP4 = (f4 < 800) ? (const float4*)(J.P + (size_t)(f4>>3)*DIM) + (f4&7) : bP1;
    bool act4 = (f4 < 800);

    float acc[4][7];
    #pragma unroll
    for (int i = 0; i < 4; i++)
        #pragma unroll
        for (int jj = 0; jj < 7; jj++) acc[i][jj] = 0.f;

    // prefetch chunk 0
    float4 pa0 = aP0[0], pa1 = aP1[0];
    float4 pb1 = bP1[0], pb2 = bP2[0], pb3 = bP3[0], pb4 = act4 ? bP4[0] : make_float4(0,0,0,0);

    for (int k0 = 0; k0 < DIM; k0 += TKC) {
        // store staged regs
        As4[r0][k4] = pa0; As4[r0+32][k4] = pa1;
        {
            int kb = (f1&7)*4, c = f1>>3;
            Bs[kb+0][c]=pb1.x; Bs[kb+1][c]=pb1.y; Bs[kb+2][c]=pb1.z; Bs[kb+3][c]=pb1.w;
            kb = (f2&7)*4; c = f2>>3;
            Bs[kb+0][c]=pb2.x; Bs[kb+1][c]=pb2.y; Bs[kb+2][c]=pb2.z; Bs[kb+3][c]=pb2.w;
            kb = (f3&7)*4; c = f3>>3;
            Bs[kb+0][c]=pb3.x; Bs[kb+1][c]=pb3.y; Bs[kb+2][c]=pb3.z; Bs[kb+3][c]=pb3.w;
            if (act4) {
                kb = (f4&7)*4; c = f4>>3;
                Bs[kb+0][c]=pb4.x; Bs[kb+1][c]=pb4.y; Bs[kb+2][c]=pb4.z; Bs[kb+3][c]=pb4.w;
            }
        }
        __syncthreads();
        if (k0 + TKC < DIM) {
            int off = (k0 + TKC) >> 2;   // in float4 units
            pa0 = aP0[off]; pa1 = aP1[off];
            pb1 = bP1[off]; pb2 = bP2[off]; pb3 = bP3[off];
            if (act4) pb4 = bP4[off];
        }
        #pragma unroll
        for (int kk4 = 0; kk4 < 8; kk4++) {
            float4 A0 = As4[ty*4+0][kk4], A1 = As4[ty*4+1][kk4];
            float4 A2 = As4[ty*4+2][kk4], A3 = As4[ty*4+3][kk4];
            float a0v[4] = {A0.x,A0.y,A0.z,A0.w};
            float a1v[4] = {A1.x,A1.y,A1.z,A1.w};
            float a2v[4] = {A2.x,A2.y,A2.z,A2.w};
            float a3v[4] = {A3.x,A3.y,A3.z,A3.w};
            #pragma unroll
            for (int s = 0; s < 4; s++) {
                const float* br = &Bs[kk4*4+s][tx*7];
                #pragma unroll
                for (int jj = 0; jj < 7; jj++) {
                    float b = br[jj];
                    acc[0][jj] += a0v[s]*b;
                    acc[1][jj] += a1v[s]*b;
                    acc[2][jj] += a2v[s]*b;
                    acc[3][jj] += a3v[s]*b;
                }
            }
        }
        __syncthreads();
    }

    float colssq[7];
    #pragma unroll
    for (int jj = 0; jj < 7; jj++) colssq[jj] = 0.f;
    #pragma unroll
    for (int i = 0; i < 4; i++) {
        int j = rowBase + ty*4 + i;
        float iv = rowInv[ty*4 + i];
        float v[7];
        #pragma unroll
        for (int jj = 0; jj < 7; jj++) { v[jj] = acc[i][jj]*iv; colssq[jj] += v[jj]*v[jj]; }
        if (j < Q) {
            #pragma unroll
            for (int jj = 0; jj < 7; jj++) {
                int c = tx*7 + jj;
                if (c < WAY) J.C[(size_t)j*WAY + c] = v[jj];
            }
        }
    }
    #pragma unroll
    for (int jj = 0; jj < 7; jj++) tmp[ty][tx*7+jj] = colssq[jj];
    __syncthreads();
    if (t < 112) {
        float s = 0.f;
        #pragma unroll
        for (int r = 0; r < 16; r++) s += tmp[r][t];
        J.part[tb*112 + t] = s;
    }
}

// ---------------- reduce partials -> scale ----------------
__global__ void k_colreduce(JSet js, const float* __restrict__ tp, int useSc2) {
    int job = blockIdx.x, t = threadIdx.x;
    if (t >= WAY) return;
    int Q = *js.cnt[job];
    int nT = (Q + TQ - 1) / TQ;
    const float* p = js.part[job];
    float s = 0.f;
    for (int tb = 0; tb < nT; tb++) s += p[tb*112 + t];
    float* o = useSc2 ? js.sc2[job] : js.sc1[job];
    o[t] = (*tp) / (sqrtf(s) + 1e-6f);
}

// ---------------- subset column norms on G ----------------
__global__ void k_colnorm_sub(JSet js, const float* __restrict__ tp) {
    int job = blockIdx.y, c = blockIdx.x;
    int Q = *js.cnt[job];
    const float* G = js.G[job];
    const int* map = js.map[job];
    __shared__ float red[256];
    float ssq = 0.f;
    for (int j = threadIdx.x; j < Q; j += 256) {
        float v = G[(size_t)map[j]*WAY + c];
        ssq += v*v;
    }
    float tot = bSum256(ssq, red);
    if (threadIdx.x == 0) js.sc1[job][c] = (*tp) / (sqrtf(tot) + 1e-6f);
}

// ---------------- cert ----------------
__global__ void k_cert(JSet js) {
    int job = blockIdx.y;
    __shared__ float ssc[WAY];
    if (threadIdx.x < WAY) ssc[threadIdx.x] = js.sc1[job][threadIdx.x];
    __syncthreads();
    int j = blockIdx.x*blockDim.x + threadIdx.x;
    if (j >= *js.cnt[job]) return;
    const int* map = js.map[job];
    int r = map ? map[j] : j;
    const float* row = js.G[job] + (size_t)r*WAY;
    float best = -3.4e38f;
    #pragma unroll 4
    for (int c = 0; c < WAY; c++) { float v = row[c]*ssc[c]; if (v > best) best = v; }
    js.cert[job][j] = best;
}

// ---------------- radix top-k ----------------
__global__ __launch_bounds__(1024) void k_topk(JSet js) {
    int job = blockIdx.x, t = threadIdx.x;
    const float* cert = js.cert[job];
    __shared__ unsigned hist[2048];
    __shared__ int ws[32];
    __shared__ unsigned shP, shM;
    __shared__ int shR;
    int Q = *js.cnt[job];
    int k = (Q < KSEL) ? Q : KSEL;
    if (t == 0) { shP = 0u; shM = 0u; shR = k; }
    __syncthreads();
    for (int pass = 0; pass < 3; pass++) {
        int shift = (pass == 0) ? 21 : ((pass == 1) ? 10 : 0);
        int nb = (pass == 2) ? 1024 : 2048;
        for (int i = t; i < 2048; i += 1024) hist[i] = 0u;
        __syncthreads();
        unsigned pfx = shP, msk = shM;
        for (int j = t; j < Q; j += 1024) {
            unsigned u = okey(cert[j]);
            if ((u & msk) == pfx) atomicAdd(&hist[(u >> shift) & (nb-1)], 1u);
        }
        __syncthreads();
        if (t == 0) {
            int rem = shR; unsigned acc = 0; int b;
            for (b = nb-1; b >= 0; b--) { unsigned h = hist[b]; if (acc + h >= (unsigned)rem) break; acc += h; }
            if (b < 0) b = 0;
            shP = pfx | ((unsigned)b << shift);
            shM = msk | ((unsigned)(nb-1) << shift);
            shR = rem - (int)acc;
        }
        __syncthreads();
    }
    unsigned Kk = shP; int rem = shR;
    __shared__ int eqB, seB;
    if (t == 0) { eqB = 0; seB = 0; }
    __syncthreads();
    for (int j0 = 0; j0 < Q; j0 += 1024) {
        int j = j0 + t, g = 0, e = 0; float v = 0.f;
        if (j < Q) { v = cert[j]; unsigned u = okey(v); g = (u > Kk); e = (u == Kk); }
        int eT; int eE = bScan1024(e, &eT, ws);
        int sel = g | (e & ((eqB + eE) < rem));
        int sT; int sE = bScan1024(sel, &sT, ws);
        if (sel) { int sl = seB + sE; js.seli[job][sl] = j; js.selv[job][sl] = v; }
        __syncthreads();
        if (t == 0) { eqB += eT; seB += sT; }
        __syncthreads();
    }
    if (t == 0) *js.selk[job] = k;
}

// ---------------- pseudo labels ----------------
__global__ void k_pseudo(JSet js) {
    int job = blockIdx.y;
    __shared__ float ssc[WAY];
    if (threadIdx.x < WAY) ssc[threadIdx.x] = js.sc1[job][threadIdx.x];
    __syncthreads();
    int i = blockIdx.x*blockDim.x + threadIdx.x;
    if (i >= *js.selk[job]) return;
    int j = js.seli[job][i];
    const int* map = js.map[job];
    int r = map ? map[j] : j;
    const float* row = js.G[job] + (size_t)r*WAY;
    float best = -3.4e38f; int bc = 0;
    for (int c = 0; c < WAY; c++) { float v = row[c]*ssc[c]; if (v > best) { best = v; bc = c; } }
    js.pse[job][i] = bc;
}

// ---------------- refined proto ----------------
__global__ void k_proto1(JSet js) {
    int job = blockIdx.y, c = blockIdx.x;
    int K = *js.selk[job];
    __shared__ int sQ[KSEL], sP[KSEL];
    __shared__ float sC[KSEL];
    const int* map = js.map[job];
    for (int i = threadIdx.x; i < K; i += 256) {
        int j = js.seli[job][i];
        int gq = map ? map[j] : j;
        sQ[i] = gq; sP[i] = js.pse[job][i];
        sC[i] = js.selv[job][i] / ((float)K * js.qn[job][gq]);
    }
    __syncthreads();
    const float* P0 = js.P0[job] + (size_t)c*DIM;
    float* P1 = js.P1[job] + (size_t)c*DIM;
    const float* A = js.A[job];
    int t = threadIdx.x;
    float acc[8];
    #pragma unroll
    for (int k = 0; k < 8; k++) acc[k] = P0[t + 256*k];
    for (int i = 0; i < K; i++) {
        if (sP[i] == c) {
            float cf = sC[i];
            const float* a = A + (size_t)sQ[i]*DIM;
            #pragma unroll
            for (int k = 0; k < 8; k++) acc[k] += cf * a[t + 256*k];
        }
    }
    #pragma unroll
    for (int k = 0; k < 8; k++) P1[t + 256*k] = acc[k];
}

// ---------------- row softmax stats ----------------
__global__ void k_rowstats(RSJ r) {
    int job = blockIdx.y;
    __shared__ float ssc[WAY];
    if (threadIdx.x < WAY) ssc[threadIdx.x] = r.sc[job][threadIdx.x];
    __syncthreads();
    int row = blockIdx.x*8 + (threadIdx.x >> 5);
    int lane = threadIdx.x & 31;
    if (row >= NQ) return;
    const float* L = r.L[job] + (size_t)row*WAY;
    float m = -3.4e38f;
    for (int c = lane; c < WAY; c += 32) m = fmaxf(m, L[c]*ssc[c]);
    #pragma unroll
    for (int o = 16; o; o >>= 1) m = fmaxf(m, __shfl_xor_sync(~0u, m, o));
    float Z = 0.f;
    for (int c = lane; c < WAY; c += 32) Z += expf(L[c]*ssc[c] - m);
    #pragma unroll
    for (int o = 16; o; o >>= 1) Z += __shfl_xor_sync(~0u, Z, o);
    float rel = 0.f;
    for (int c = lane; c < WAY; c += 32) {
        float p = expf(L[c]*ssc[c] - m) / Z;
        rel += p * logf(p + 1e-10f);
    }
    #pragma unroll
    for (int o = 16; o; o >>= 1) rel += __shfl_xor_sync(~0u, rel, o);
    if (lane == 0) { r.absc[job][row] = m; r.relc[job][row] = rel; }
}

// ---------------- partition ----------------
__global__ __launch_bounds__(1024) void k_partition(
    const float* __restrict__ ar, const float* __restrict__ ad,
    const float* __restrict__ rr, const float* __restrict__ rd,
    int* __restrict__ resI, int* __restrict__ dctI,
    int* __restrict__ cnts, float* __restrict__ out)
{
    int t = threadIdx.x;
    __shared__ int ws[32];
    __shared__ int rb, Rs;
    if (t == 0) rb = 0;
    __syncthreads();
    for (int j0 = 0; j0 < NQ; j0 += 1024) {
        int j = j0 + t, f = 0;
        if (j < NQ) f = ((ar[j]-ad[j]+rr[j]-rd[j]) > 0.f);
        int tot; int ex = bScan1024(f, &tot, ws);
        if (f) { int sl = rb + ex; resI[sl] = j; out[2+sl] = (float)j; }
        __syncthreads();
        if (t == 0) rb += tot;
        __syncthreads();
    }
    if (t == 0) { Rs = rb; cnts[0] = rb; rb = 0; }
    __syncthreads();
    int R = Rs;
    for (int j0 = 0; j0 < NQ; j0 += 1024) {
        int j = j0 + t, f = 0;
        if (j < NQ) f = ((ar[j]-ad[j]+rr[j]-rd[j]) < 0.f);
        int tot; int ex = bScan1024(f, &tot, ws);
        if (f) { int sl = rb + ex; dctI[sl] = j; out[2+R+sl] = (float)j; }
        __syncthreads();
        if (t == 0) rb += tot;
        __syncthreads();
    }
    if (t == 0) cnts[1] = rb;
}

// ---------------- weights ----------------
__global__ void k_w(const float* __restrict__ ar, const float* __restrict__ ad,
                    const int* __restrict__ cnts, float* __restrict__ out) {
    int q = blockIdx.x*blockDim.x + threadIdx.x;
    if (q >= NQ) return;
    int base = 2 + cnts[0] + cnts[1];
    float a = ar[q], b = ad[q], den = fmaxf(a+b, 1e-8f);
    out[base + q] = a/den;
    out[base + NQ + q] = b/den;
}

// ---------------- per-class KL ----------------
__global__ void k_classkl(KLJ kj) {
    int pr = blockIdx.y, c = blockIdx.x;
    int Q = *kj.cnt[pr];
    const float* Lh = kj.Lh[pr];
    const float* Ll = kj.Ll[pr];
    float sh = kj.sch[pr][c], sl = kj.scl[pr][c];
    __shared__ float red[256];
    float mh = -3.4e38f, ml = -3.4e38f;
    for (int j = threadIdx.x; j < Q; j += 256) {
        mh = fmaxf(mh, Lh[(size_t)j*WAY+c]*sh);
        ml = fmaxf(ml, Ll[(size_t)j*WAY+c]*sl);
    }
    mh = bMax256(mh, red); ml = bMax256(ml, red);
    float Zh = 0.f, Zl = 0.f;
    for (int j = threadIdx.x; j < Q; j += 256) {
        Zh += expf(Lh[(size_t)j*WAY+c]*sh - mh);
        Zl += expf(Ll[(size_t)j*WAY+c]*sl - ml);
    }
    Zh = bSum256(Zh, red); Zl = bSum256(Zl, red);
    float lZl = logf(Zl), s = 0.f;
    for (int j = threadIdx.x; j < Q; j += 256) {
        float lh = Lh[(size_t)j*WAY+c]*sh, ll = Ll[(size_t)j*WAY+c]*sl;
        float p = expf(lh - mh) / Zh;
        s += p * (logf(p) - (ll - ml - lZl));
    }
    s = bSum256(s, red);
    if (threadIdx.x == 0) kj.kl[pr][c] = s;
}

// ---------------- finalize (2 blocks) ----------------
__global__ void k_finalize(FinJ f) {
    int b = blockIdx.x;
    __shared__ float red[256];
    int Q = *f.cnt[b];
    float s = 0.f;
    for (int c = threadIdx.x; c < WAY; c += 256) s += f.kl[b][c];
    s = bSum256(s, red);
    float sw = 0.f;
    for (int j = threadIdx.x; j < Q; j += 256) sw += f.absc[b][f.idx[b][j]];
    sw = bSum256(sw, red);
    if (threadIdx.x == 0) {
        float w0 = (Q > 0) ? f.absc[b][f.idx[b][0]] : 0.f;
        *f.slot[b] = (*f.tsc[b]) * (w0 * s / (sw + 1e-8f));
    }
}

// ---------------- host ----------------
extern "C" void kernel_launch(void* const* d_in, const int* in_sizes, int n_in,
                              void* d_out, int out_size)
{
    const float* x_shot    = (const float*)d_in[0];
    const float* x_query   = (const float*)d_in[1];
    const float* dct_shot  = (const float*)d_in[2];
    const float* dct_query = (const float*)d_in[3];
    const float* tp        = (const float*)d_in[4];
    const float* temp      = (const float*)d_in[5];
    const float* temp_dct  = (const float*)d_in[6];
    float* out = (float*)d_out;

    float* B = nullptr; int* IB = nullptr; int* FC = nullptr;
    cudaGetSymbolAddress((void**)&B, g_buf);
    cudaGetSymbolAddress((void**)&IB, g_ibuf);
    cudaGetSymbolAddress((void**)&FC, g_fullCnt);

    float* P0 = B + O_P0;     float* P1 = B + O_P1;
    float* QN = B + O_QN;     float* G = B + O_G;
    float* L = B + O_L;       float* CERT = B + O_CERT;
    float* SELV = B + O_SELV;
    float* ABSR = B + O_STAT; float* ABSD = ABSR + NQ;
    float* RELR = ABSD + NQ;  float* RELD = RELR + NQ;
    float* SC1 = B + O_SC1;   float* SC2 = B + O_SC2;
    float* KL = B + O_KL;     float* PART = B + O_PART;
    int* RES = IB + IO_RES;   int* DCT = IB + IO_DCT;
    int* SELI = IB + IO_SELI; int* PSE = IB + IO_PSE;
    int* SELK = IB + IO_SELK; int* CNTS = IB + IO_CNTS;
    const int* CR = CNTS;     const int* CD = CNTS + 1;

    const float* Aq[2] = { x_query, dct_query };

    // -------- phase 1 (2 jobs) --------
    JSet j1 = {};
    for (int s = 0; s < 2; s++) {
        j1.A[s] = Aq[s]; j1.qn[s] = QN + s*NQ;
        j1.P0[s] = P0 + s*SLP; j1.G[s] = G + (size_t)s*NQ*WAY;
        j1.map[s] = nullptr; j1.cnt[s] = FC;
        j1.P1[s] = P1 + s*SLP;
        j1.cert[s] = CERT + s*NQ; j1.selv[s] = SELV + s*KSEL;
        j1.sc1[s] = SC1 + s*WAY; j1.sc2[s] = SC2 + s*WAY;
        j1.seli[s] = SELI + s*KSEL; j1.selk[s] = SELK + s; j1.pse[s] = PSE + s*KSEL;
        j1.part[s] = PART + s*NT*112;
    }
    k_proto0<<<dim3(WAY,2), 256>>>(x_shot, dct_shot, P0, P0 + SLP);
    k_qnorm<<<dim3(NQ,2), 256>>>(x_query, dct_query, QN, QN + NQ);

    GJobs g1 = {};
    for (int s = 0; s < 2; s++)
        g1.j[s] = { Aq[s], QN + s*NQ, P0 + s*SLP, G + (size_t)s*NQ*WAY,
                    PART + s*NT*112, nullptr, FC };
    k_gemm<<<2*NT, 256>>>(g1);
    k_colreduce<<<2, 128>>>(j1, tp, 0);
    k_cert<<<dim3((NQ+255)/256, 2), 256>>>(j1);
    k_topk<<<2, 1024>>>(j1);
    k_pseudo<<<dim3(2,2), 256>>>(j1);
    k_proto1<<<dim3(WAY,2), 256>>>(j1);

    GJobs g2 = {};
    for (int s = 0; s < 2; s++)
        g2.j[s] = { Aq[s], QN + s*NQ, P1 + s*SLP, L + (size_t)s*NQ*WAY,
                    PART + s*NT*112, nullptr, FC };
    k_gemm<<<2*NT, 256>>>(g2);
    k_colreduce<<<2, 128>>>(j1, tp, 1);

    RSJ rs;
    rs.L[0] = L; rs.L[1] = L + (size_t)NQ*WAY;
    rs.sc[0] = SC2; rs.sc[1] = SC2 + WAY;
    rs.absc[0] = ABSR; rs.absc[1] = ABSD;
    rs.relc[0] = RELR; rs.relc[1] = RELD;
    k_rowstats<<<dim3((NQ+7)/8, 2), 256>>>(rs);

    k_partition<<<1, 1024>>>(ABSR, ABSD, RELR, RELD, RES, DCT, CNTS, out);
    k_w<<<(NQ+255)/256, 256>>>(ABSR, ABSD, CNTS, out);

    // -------- phase 3 (4 jobs): 0 x/RES  1 dct/RES  2 dct/DCT  3 x/DCT --------
    int src[4] = { 0, 1, 1, 0 };
    const int* mp[4] = { RES, RES, DCT, DCT };
    const int* cn[4] = { CR, CR, CD, CD };
    JSet j3 = {};
    for (int s = 0; s < 4; s++) {
        int u = src[s];
        j3.A[s] = Aq[u]; j3.qn[s] = QN + u*NQ;
        j3.P0[s] = P0 + u*SLP; j3.G[s] = G + (size_t)u*NQ*WAY;
        j3.map[s] = mp[s]; j3.cnt[s] = cn[s];
        j3.P1[s] = P1 + s*SLP;
        j3.cert[s] = CERT + s*NQ; j3.selv[s] = SELV + s*KSEL;
        j3.sc1[s] = SC1 + s*WAY; j3.sc2[s] = SC2 + s*WAY;
        j3.seli[s] = SELI + s*KSEL; j3.selk[s] = SELK + s; j3.pse[s] = PSE + s*KSEL;
        j3.part[s] = PART + s*NT*112;
    }
    k_colnorm_sub<<<dim3(WAY,4), 256>>>(j3, tp);
    k_cert<<<dim3((NQ+255)/256, 4), 256>>>(j3);
    k_topk<<<4, 1024>>>(j3);
    k_pseudo<<<dim3(2,4), 256>>>(j3);
    k_proto1<<<dim3(WAY,4), 256>>>(j3);

    GJobs g3 = {};
    for (int s = 0; s < 4; s++)
        g3.j[s] = { j3.A[s], j3.qn[s], P1 + s*SLP, L + (size_t)s*NQ*WAY,
                    PART + s*NT*112, mp[s], cn[s] };
    k_gemm<<<4*NT, 256>>>(g3);
    k_colreduce<<<4, 128>>>(j3, tp, 1);

    KLJ kj;
    kj.Lh[0] = L;                     kj.sch[0] = SC2;
    kj.Ll[0] = L + (size_t)NQ*WAY;    kj.scl[0] = SC2 + WAY;
    kj.cnt[0] = CR; kj.kl[0] = KL;
    kj.Lh[1] = L + (size_t)2*NQ*WAY;  kj.sch[1] = SC2 + 2*WAY;
    kj.Ll[1] = L + (size_t)3*NQ*WAY;  kj.scl[1] = SC2 + 3*WAY;
    kj.cnt[1] = CD; kj.kl[1] = KL + WAY;
    k_classkl<<<dim3(WAY,2), 256>>>(kj);

    FinJ fj;
    fj.kl[0] = KL;       fj.absc[0] = ABSR; fj.idx[0] = RES; fj.cnt[0] = CR;
    fj.tsc[0] = temp_dct; fj.slot[0] = out + 1;
    fj.kl[1] = KL + WAY; fj.absc[1] = ABSD; fj.idx[1] = DCT; fj.cnt[1] = CD;
    fj.tsc[1] = temp;    fj.slot[1] = out + 0;
    k_finalize<<<2, 256>>>(fj);
}

// round 5
// speedup vs baseline: 2.8719x; 1.1317x over previous
#include <cuda_runtime.h>
#include <math.h>
#include <stdint.h>

#define WAY   100
#define SHOT  5
#define DIM   2048
#define NQ    10000
#define KSEL  512
#define TQ    64
#define TKC   32
#define NT    157
#define BSS   113

// ---------------- static scratch ----------------
#define SLP (WAY*DIM)
#define O_P0   0
#define O_P1   (O_P0 + 2*SLP)
#define O_QN   (O_P1 + 4*SLP)
#define O_G    (O_QN + 2*NQ)
#define O_L    (O_G  + 2*NQ*WAY)
#define O_CERT (O_L  + 4*NQ*WAY)
#define O_SELV (O_CERT + 4*NQ)
#define O_STAT (O_SELV + 4*KSEL)
#define O_SC1  (O_STAT + 4*NQ)
#define O_SC2  (O_SC1 + 4*WAY)
#define O_KL   (O_SC2 + 4*WAY)
#define O_PART (O_KL + 2*WAY)
#define TOTF   (O_PART + 4*NT*112)
__device__ float g_buf[TOTF];

#define IO_RES  0
#define IO_DCT  NQ
#define IO_SELI (2*NQ)
#define IO_PSE  (2*NQ+4*KSEL)
#define IO_SELK (2*NQ+8*KSEL)
#define IO_CNTS (2*NQ+8*KSEL+4)
__device__ int g_ibuf[2*NQ+8*KSEL+8];
__device__ int g_fullCnt = NQ;

// ---------------- job structs ----------------
struct GJob { const float* A; const float* qn; const float* P; float* C;
              float* part; const int* map; const int* cnt; };
struct GJobs { GJob j[4]; };
struct JSet {
    const float* A[4]; const float* qn[4]; const float* P0[4]; const float* G[4];
    const int* map[4]; const int* cnt[4];
    float* P1[4]; float* cert[4]; float* selv[4]; float* sc1[4]; float* sc2[4];
    int* seli[4]; int* selk[4]; int* pse[4];
    const float* part[4];
};
struct RSJ { const float* L[2]; const float* sc[2]; float* absc[2]; float* relc[2]; };
struct KLJ { const float* Lh[2]; const float* sch[2]; const float* Ll[2];
             const float* scl[2]; const int* cnt[2]; float* kl[2]; };
struct FinJ { const float* kl[2]; const float* absc[2]; const int* idx[2];
              const int* cnt[2]; const float* tsc[2]; float* slot[2]; };

// ---------------- reductions ----------------
__device__ __forceinline__ float bSum256(float v, float* s) {
    int t = threadIdx.x; __syncthreads(); s[t] = v; __syncthreads();
    #pragma unroll
    for (int o = 128; o > 0; o >>= 1) { if (t < o) s[t] += s[t+o]; __syncthreads(); }
    float r = s[0]; __syncthreads(); return r;
}
__device__ __forceinline__ float bMax256(float v, float* s) {
    int t = threadIdx.x; __syncthreads(); s[t] = v; __syncthreads();
    #pragma unroll
    for (int o = 128; o > 0; o >>= 1) { if (t < o) s[t] = fmaxf(s[t], s[t+o]); __syncthreads(); }
    float r = s[0]; __syncthreads(); return r;
}
__device__ __forceinline__ int bScan1024(int v, int* tot, int* ws) {
    int t = threadIdx.x, lane = t & 31, w = t >> 5, x = v;
    #pragma unroll
    for (int o = 1; o < 32; o <<= 1) { int y = __shfl_up_sync(~0u, x, o); if (lane >= o) x += y; }
    if (lane == 31) ws[w] = x;
    __syncthreads();
    if (w == 0) {
        int s2 = ws[lane];
        #pragma unroll
        for (int o = 1; o < 32; o <<= 1) { int y = __shfl_up_sync(~0u, s2, o); if (lane >= o) s2 += y; }
        ws[lane] = s2;
    }
    __syncthreads();
    int r = (w ? ws[w-1] : 0) + x - v; *tot = ws[31]; __syncthreads(); return r;
}
__device__ __forceinline__ unsigned okey(float f) {
    unsigned u = __float_as_uint(f);
    return (u & 0x80000000u) ? ~u : (u | 0x80000000u);
}

// ---------------- proto0 (2 jobs) ----------------
__global__ void k_proto0(const float* __restrict__ s0, const float* __restrict__ s1,
                         float* __restrict__ p0, float* __restrict__ p1) {
    const float* shot = blockIdx.y ? s1 : s0;
    float* proto = blockIdx.y ? p1 : p0;
    int c = blockIdx.x;
    __shared__ float red[256];
    const float4* sB = (const float4*)(shot + (size_t)c*SHOT*DIM);
    float4* pB = (float4*)(proto + (size_t)c*DIM);
    float ssq = 0.f;
    for (int d = threadIdx.x; d < DIM/4; d += 256) {
        float4 a = make_float4(0,0,0,0);
        #pragma unroll
        for (int s = 0; s < SHOT; s++) {
            float4 v = sB[s*(DIM/4)+d];
            a.x += v.x; a.y += v.y; a.z += v.z; a.w += v.w;
        }
        a.x *= 0.2f; a.y *= 0.2f; a.z *= 0.2f; a.w *= 0.2f;
        pB[d] = a;
        ssq += a.x*a.x + a.y*a.y + a.z*a.z + a.w*a.w;
    }
    float tot = bSum256(ssq, red);
    __shared__ float inv;
    if (threadIdx.x == 0) inv = 1.f / fmaxf(sqrtf(tot), 1e-12f);
    __syncthreads();
    for (int d = threadIdx.x; d < DIM/4; d += 256) {
        float4 a = pB[d]; a.x *= inv; a.y *= inv; a.z *= inv; a.w *= inv; pB[d] = a;
    }
}

// ---------------- query norms (2 jobs) — exact R3 numerics ----------------
__global__ void k_qnorm(const float* __restrict__ x0, const float* __restrict__ x1,
                        float* __restrict__ q0, float* __restrict__ q1) {
    const float* X = blockIdx.y ? x1 : x0;
    float* qn = blockIdx.y ? q1 : q0;
    __shared__ float red[256];
    const float4* row = (const float4*)(X + (size_t)blockIdx.x*DIM);
    float ssq = 0.f;
    #pragma unroll
    for (int i = 0; i < 2; i++) {
        float4 v = row[threadIdx.x + 256*i];
        ssq += v.x*v.x + v.y*v.y + v.z*v.z + v.w*v.w;
    }
    float tot = bSum256(ssq, red);
    if (threadIdx.x == 0) qn[blockIdx.x] = fmaxf(sqrtf(tot), 1e-12f);
}

// ---------------- GEMM (R3-exact) ----------------
__global__ __launch_bounds__(256) void k_gemm(GJobs g) {
    __shared__ float4 As4[TQ][8];
    __shared__ float Bs[TKC][BSS];
    __shared__ float tmp[16][112];
    __shared__ int rowIdx[TQ];
    __shared__ float rowInv[TQ];

    int job = blockIdx.x / NT, tb = blockIdx.x - job*NT;
    GJob J = g.j[job];
    int Q = *J.cnt;
    int rowBase = tb * TQ;
    if (rowBase >= Q) return;

    int t = threadIdx.x, tx = t & 15, ty = t >> 4;

    for (int i = t; i < TKC*13; i += 256) Bs[i/13][100 + i%13] = 0.f;
    if (t < TQ) {
        int j = rowBase + t; int gq = 0; float iv = 0.f;
        if (j < Q) { gq = J.map ? J.map[j] : j; iv = 1.f / J.qn[gq]; }
        rowIdx[t] = gq; rowInv[t] = iv;
    }
    __syncthreads();

    int r0 = t >> 3, k4 = t & 7;
    const float4* aP0 = (const float4*)(J.A + (size_t)rowIdx[r0]*DIM) + k4;
    const float4* aP1 = (const float4*)(J.A + (size_t)rowIdx[r0+32]*DIM) + k4;
    int f1 = t, f2 = t+256, f3 = t+512, f4 = t+768;
    const float4* bP1 = (const float4*)(J.P + (size_t)(f1>>3)*DIM) + (f1&7);
    const float4* bP2 = (const float4*)(J.P + (size_t)(f2>>3)*DIM) + (f2&7);
    const float4* bP3 = (const float4*)(J.P + (size_t)(f3>>3)*DIM) + (f3&7);
    const float4* bP4 = (f4 < 800) ? (const float4*)(J.P + (size_t)(f4>>3)*DIM) + (f4&7) : bP1;
    bool act4 = (f4 < 800);

    float acc[4][7];
    #pragma unroll
    for (int i = 0; i < 4; i++)
        #pragma unroll
        for (int jj = 0; jj < 7; jj++) acc[i][jj] = 0.f;

    float4 pa0 = aP0[0], pa1 = aP1[0];
    float4 pb1 = bP1[0], pb2 = bP2[0], pb3 = bP3[0], pb4 = act4 ? bP4[0] : make_float4(0,0,0,0);

    for (int k0 = 0; k0 < DIM; k0 += TKC) {
        As4[r0][k4] = pa0; As4[r0+32][k4] = pa1;
        {
            int kb = (f1&7)*4, c = f1>>3;
            Bs[kb+0][c]=pb1.x; Bs[kb+1][c]=pb1.y; Bs[kb+2][c]=pb1.z; Bs[kb+3][c]=pb1.w;
            kb = (f2&7)*4; c = f2>>3;
            Bs[kb+0][c]=pb2.x; Bs[kb+1][c]=pb2.y; Bs[kb+2][c]=pb2.z; Bs[kb+3][c]=pb2.w;
            kb = (f3&7)*4; c = f3>>3;
            Bs[kb+0][c]=pb3.x; Bs[kb+1][c]=pb3.y; Bs[kb+2][c]=pb3.z; Bs[kb+3][c]=pb3.w;
            if (act4) {
                kb = (f4&7)*4; c = f4>>3;
                Bs[kb+0][c]=pb4.x; Bs[kb+1][c]=pb4.y; Bs[kb+2][c]=pb4.z; Bs[kb+3][c]=pb4.w;
            }
        }
        __syncthreads();
        if (k0 + TKC < DIM) {
            int off = (k0 + TKC) >> 2;
            pa0 = aP0[off]; pa1 = aP1[off];
            pb1 = bP1[off]; pb2 = bP2[off]; pb3 = bP3[off];
            if (act4) pb4 = bP4[off];
        }
        #pragma unroll
        for (int kk4 = 0; kk4 < 8; kk4++) {
            float4 A0 = As4[ty*4+0][kk4], A1 = As4[ty*4+1][kk4];
            float4 A2 = As4[ty*4+2][kk4], A3 = As4[ty*4+3][kk4];
            float a0v[4] = {A0.x,A0.y,A0.z,A0.w};
            float a1v[4] = {A1.x,A1.y,A1.z,A1.w};
            float a2v[4] = {A2.x,A2.y,A2.z,A2.w};
            float a3v[4] = {A3.x,A3.y,A3.z,A3.w};
            #pragma unroll
            for (int s = 0; s < 4; s++) {
                const float* br = &Bs[kk4*4+s][tx*7];
                #pragma unroll
                for (int jj = 0; jj < 7; jj++) {
                    float b = br[jj];
                    acc[0][jj] += a0v[s]*b;
                    acc[1][jj] += a1v[s]*b;
                    acc[2][jj] += a2v[s]*b;
                    acc[3][jj] += a3v[s]*b;
                }
            }
        }
        __syncthreads();
    }

    float colssq[7];
    #pragma unroll
    for (int jj = 0; jj < 7; jj++) colssq[jj] = 0.f;
    #pragma unroll
    for (int i = 0; i < 4; i++) {
        int j = rowBase + ty*4 + i;
        float iv = rowInv[ty*4 + i];
        float v[7];
        #pragma unroll
        for (int jj = 0; jj < 7; jj++) { v[jj] = acc[i][jj]*iv; colssq[jj] += v[jj]*v[jj]; }
        if (j < Q) {
            #pragma unroll
            for (int jj = 0; jj < 7; jj++) {
                int c = tx*7 + jj;
                if (c < WAY) J.C[(size_t)j*WAY + c] = v[jj];
            }
        }
    }
    #pragma unroll
    for (int jj = 0; jj < 7; jj++) tmp[ty][tx*7+jj] = colssq[jj];
    __syncthreads();
    if (t < 112) {
        float s = 0.f;
        #pragma unroll
        for (int r = 0; r < 16; r++) s += tmp[r][t];
        J.part[tb*112 + t] = s;
    }
}

// ---- reduce partials -> scale (serial tb order = R3-bitwise; unrolled loads) ----
__global__ void k_colreduce(JSet js, const float* __restrict__ tp,
                            int useSc2, int fixedNT) {
    int job = blockIdx.x, t = threadIdx.x;
    if (t >= WAY) return;
    int nT = fixedNT ? fixedNT : (*js.cnt[job] + TQ - 1) / TQ;
    const float* p = js.part[job] + t;
    float s = 0.f;
    #pragma unroll 4
    for (int tb = 0; tb < nT; tb++) s += p[(size_t)tb*112];
    float* o = useSc2 ? js.sc2[job] : js.sc1[job];
    o[t] = (*tp) / (sqrtf(s) + 1e-6f);
}

// ---------------- coalesced subset colnorm partials (loss path only) ----------------
__global__ void k_subpart(const float* __restrict__ Gr, const float* __restrict__ Gd,
                          const float* __restrict__ ar, const float* __restrict__ ad,
                          const float* __restrict__ rr, const float* __restrict__ rd,
                          float* __restrict__ part) {
    int tile = blockIdx.x, s = blockIdx.y;
    int c = threadIdx.x;   // 128 threads
    const float* G = s ? Gd : Gr;
    float sR = 0.f, sD = 0.f;
    int j0 = tile * TQ;
    int jend = j0 + TQ; if (jend > NQ) jend = NQ;
    for (int j = j0; j < jend; j++) {
        float diff = ar[j] - ad[j] + rr[j] - rd[j];
        float v = (c < WAY) ? G[(size_t)j*WAY + c] : 0.f;
        float v2 = v*v;
        if (diff > 0.f) sR += v2;
        if (diff < 0.f) sD += v2;
    }
    if (c < 112) {
        part[((size_t)(2*s+0)*NT + tile)*112 + c] = sR;
        part[((size_t)(2*s+1)*NT + tile)*112 + c] = sD;
    }
}

// ---------------- cert ----------------
__global__ void k_cert(JSet js) {
    int job = blockIdx.y;
    __shared__ float ssc[WAY];
    if (threadIdx.x < WAY) ssc[threadIdx.x] = js.sc1[job][threadIdx.x];
    __syncthreads();
    int j = blockIdx.x*blockDim.x + threadIdx.x;
    if (j >= *js.cnt[job]) return;
    const int* map = js.map[job];
    int r = map ? map[j] : j;
    const float* row = js.G[job] + (size_t)r*WAY;
    float best = -3.4e38f;
    #pragma unroll 4
    for (int c = 0; c < WAY; c++) { float v = row[c]*ssc[c]; if (v > best) best = v; }
    js.cert[job][j] = best;
}

// ------- radix top-k (integer-exact parallel threshold) + fused pseudo -------
__global__ __launch_bounds__(1024) void k_topk(JSet js) {
    int job = blockIdx.x, t = threadIdx.x;
    const float* cert = js.cert[job];
    __shared__ unsigned hist[2048];
    __shared__ int ws[32];
    __shared__ unsigned shP, shM;
    __shared__ int shR;
    __shared__ float ssc[WAY];
    int Q = *js.cnt[job];
    int k = (Q < KSEL) ? Q : KSEL;
    if (t == 0) { shP = 0u; shM = 0u; shR = k; }
    __syncthreads();
    for (int pass = 0; pass < 3; pass++) {
        int shift = (pass == 0) ? 21 : ((pass == 1) ? 10 : 0);
        int nb = (pass == 2) ? 1024 : 2048;
        for (int i = t; i < 2048; i += 1024) hist[i] = 0u;
        __syncthreads();
        unsigned pfx = shP, msk = shM;
        int rem = shR;
        for (int j = t; j < Q; j += 1024) {
            unsigned u = okey(cert[j]);
            if ((u & msk) == pfx) atomicAdd(&hist[(u >> shift) & (nb-1)], 1u);
        }
        __syncthreads();
        int i0 = nb - 1 - 2*t, i1 = nb - 2 - 2*t;
        int h0 = (i0 >= 0) ? (int)hist[i0] : 0;
        int h1 = (i1 >= 0) ? (int)hist[i1] : 0;
        int tot; int ex = bScan1024(h0 + h1, &tot, ws);
        if (i0 >= 0 && ex < rem && ex + h0 >= rem) {
            shP = pfx | ((unsigned)i0 << shift);
            shM = msk | ((unsigned)(nb-1) << shift);
            shR = rem - ex;
        } else if (i1 >= 0 && ex + h0 < rem && ex + h0 + h1 >= rem) {
            shP = pfx | ((unsigned)i1 << shift);
            shM = msk | ((unsigned)(nb-1) << shift);
            shR = rem - ex - h0;
        }
        __syncthreads();
    }
    unsigned Kk = shP; int rem = shR;
    __shared__ int eqB, seB;
    if (t == 0) { eqB = 0; seB = 0; }
    __syncthreads();
    for (int j0 = 0; j0 < Q; j0 += 1024) {
        int j = j0 + t, g = 0, e = 0; float v = 0.f;
        if (j < Q) { v = cert[j]; unsigned u = okey(v); g = (u > Kk); e = (u == Kk); }
        int eT; int eE = bScan1024(e, &eT, ws);
        int sel = g | (e & ((eqB + eE) < rem));
        int sT; int sE = bScan1024(sel, &sT, ws);
        if (sel) { int sl = seB + sE; js.seli[job][sl] = j; js.selv[job][sl] = v; }
        __syncthreads();
        if (t == 0) { eqB += eT; seB += sT; }
        __syncthreads();
    }
    if (t == 0) *js.selk[job] = k;
    // fused pseudo labels (same per-row argmax order as before)
    if (t < WAY) ssc[t] = js.sc1[job][t];
    __syncthreads();
    const int* map = js.map[job];
    for (int i = t; i < k; i += 1024) {
        int j = js.seli[job][i];
        int r = map ? map[j] : j;
        const float* row = js.G[job] + (size_t)r*WAY;
        float best = -3.4e38f; int bc = 0;
        for (int c = 0; c < WAY; c++) { float v = row[c]*ssc[c]; if (v > best) { best = v; bc = c; } }
        js.pse[job][i] = bc;
    }
}

// ---------------- refined proto ----------------
__global__ void k_proto1(JSet js) {
    int job = blockIdx.y, c = blockIdx.x;
    int K = *js.selk[job];
    __shared__ int sQ[KSEL], sP[KSEL];
    __shared__ float sC[KSEL];
    const int* map = js.map[job];
    for (int i = threadIdx.x; i < K; i += 256) {
        int j = js.seli[job][i];
        int gq = map ? map[j] : j;
        sQ[i] = gq; sP[i] = js.pse[job][i];
        sC[i] = js.selv[job][i] / ((float)K * js.qn[job][gq]);
    }
    __syncthreads();
    const float* P0 = js.P0[job] + (size_t)c*DIM;
    float* P1 = js.P1[job] + (size_t)c*DIM;
    const float* A = js.A[job];
    int t = threadIdx.x;
    float acc[8];
    #pragma unroll
    for (int kq = 0; kq < 8; kq++) acc[kq] = P0[t + 256*kq];
    for (int i = 0; i < K; i++) {
        if (sP[i] == c) {
            float cf = sC[i];
            const float* a = A + (size_t)sQ[i]*DIM;
            #pragma unroll
            for (int kq = 0; kq < 8; kq++) acc[kq] += cf * a[t + 256*kq];
        }
    }
    #pragma unroll
    for (int kq = 0; kq < 8; kq++) P1[t + 256*kq] = acc[kq];
}

// ---------------- row softmax stats ----------------
__global__ void k_rowstats(RSJ r) {
    int job = blockIdx.y;
    __shared__ float ssc[WAY];
    if (threadIdx.x < WAY) ssc[threadIdx.x] = r.sc[job][threadIdx.x];
    __syncthreads();
    int row = blockIdx.x*8 + (threadIdx.x >> 5);
    int lane = threadIdx.x & 31;
    if (row >= NQ) return;
    const float* L = r.L[job] + (size_t)row*WAY;
    float m = -3.4e38f;
    for (int c = lane; c < WAY; c += 32) m = fmaxf(m, L[c]*ssc[c]);
    #pragma unroll
    for (int o = 16; o; o >>= 1) m = fmaxf(m, __shfl_xor_sync(~0u, m, o));
    float Z = 0.f;
    for (int c = lane; c < WAY; c += 32) Z += expf(L[c]*ssc[c] - m);
    #pragma unroll
    for (int o = 16; o; o >>= 1) Z += __shfl_xor_sync(~0u, Z, o);
    float rel = 0.f;
    for (int c = lane; c < WAY; c += 32) {
        float p = expf(L[c]*ssc[c] - m) / Z;
        rel += p * logf(p + 1e-10f);
    }
    #pragma unroll
    for (int o = 16; o; o >>= 1) rel += __shfl_xor_sync(~0u, rel, o);
    if (lane == 0) { r.absc[job][row] = m; r.relc[job][row] = rel; }
}

// ---------------- partition + fused weights ----------------
__global__ __launch_bounds__(1024) void k_partition(
    const float* __restrict__ ar, const float* __restrict__ ad,
    const float* __restrict__ rr, const float* __restrict__ rd,
    int* __restrict__ resI, int* __restrict__ dctI,
    int* __restrict__ cnts, float* __restrict__ out)
{
    int t = threadIdx.x;
    __shared__ int ws[32];
    __shared__ int rb, Rs;
    if (t == 0) rb = 0;
    __syncthreads();
    for (int j0 = 0; j0 < NQ; j0 += 1024) {
        int j = j0 + t, f = 0;
        if (j < NQ) f = ((ar[j]-ad[j]+rr[j]-rd[j]) > 0.f);
        int tot; int ex = bScan1024(f, &tot, ws);
        if (f) { int sl = rb + ex; resI[sl] = j; out[2+sl] = (float)j; }
        __syncthreads();
        if (t == 0) rb += tot;
        __syncthreads();
    }
    if (t == 0) { Rs = rb; cnts[0] = rb; rb = 0; }
    __syncthreads();
    int R = Rs;
    for (int j0 = 0; j0 < NQ; j0 += 1024) {
        int j = j0 + t, f = 0;
        if (j < NQ) f = ((ar[j]-ad[j]+rr[j]-rd[j]) < 0.f);
        int tot; int ex = bScan1024(f, &tot, ws);
        if (f) { int sl = rb + ex; dctI[sl] = j; out[2+R+sl] = (float)j; }
        __syncthreads();
        if (t == 0) rb += tot;
        __syncthreads();
    }
    if (t == 0) cnts[1] = rb;
    __syncthreads();
    int base = 2 + R + rb;
    for (int q = t; q < NQ; q += 1024) {
        float a = ar[q], b = ad[q], den = fmaxf(a+b, 1e-8f);
        out[base + q] = a/den;
        out[base + NQ + q] = b/den;
    }
}

// ---------------- per-class KL ----------------
__global__ void k_classkl(KLJ kj) {
    int pr = blockIdx.y, c = blockIdx.x;
    int Q = *kj.cnt[pr];
    const float* Lh = kj.Lh[pr];
    const float* Ll = kj.Ll[pr];
    float sh = kj.sch[pr][c], sl = kj.scl[pr][c];
    __shared__ float red[256];
    float mh = -3.4e38f, ml = -3.4e38f;
    for (int j = threadIdx.x; j < Q; j += 256) {
        mh = fmaxf(mh, Lh[(size_t)j*WAY+c]*sh);
        ml = fmaxf(ml, Ll[(size_t)j*WAY+c]*sl);
    }
    mh = bMax256(mh, red); ml = bMax256(ml, red);
    float Zh = 0.f, Zl = 0.f;
    for (int j = threadIdx.x; j < Q; j += 256) {
        Zh += expf(Lh[(size_t)j*WAY+c]*sh - mh);
        Zl += expf(Ll[(size_t)j*WAY+c]*sl - ml);
    }
    Zh = bSum256(Zh, red); Zl = bSum256(Zl, red);
    float lZl = logf(Zl), s = 0.f;
    for (int j = threadIdx.x; j < Q; j += 256) {
        float lh = Lh[(size_t)j*WAY+c]*sh, ll = Ll[(size_t)j*WAY+c]*sl;
        float p = expf(lh - mh) / Zh;
        s += p * (logf(p) - (ll - ml - lZl));
    }
    s = bSum256(s, red);
    if (threadIdx.x == 0) kj.kl[pr][c] = s;
}

// ---------------- finalize ----------------
__global__ void k_finalize(FinJ f) {
    int b = blockIdx.x;
    __shared__ float red[256];
    int Q = *f.cnt[b];
    float s = 0.f;
    for (int c = threadIdx.x; c < WAY; c += 256) s += f.kl[b][c];
    s = bSum256(s, red);
    float sw = 0.f;
    for (int j = threadIdx.x; j < Q; j += 256) sw += f.absc[b][f.idx[b][j]];
    sw = bSum256(sw, red);
    if (threadIdx.x == 0) {
        float w0 = (Q > 0) ? f.absc[b][f.idx[b][0]] : 0.f;
        *f.slot[b] = (*f.tsc[b]) * (w0 * s / (sw + 1e-8f));
    }
}

// ---------------- host ----------------
extern "C" void kernel_launch(void* const* d_in, const int* in_sizes, int n_in,
                              void* d_out, int out_size)
{
    const float* x_shot    = (const float*)d_in[0];
    const float* x_query   = (const float*)d_in[1];
    const float* dct_shot  = (const float*)d_in[2];
    const float* dct_query = (const float*)d_in[3];
    const float* tp        = (const float*)d_in[4];
    const float* temp      = (const float*)d_in[5];
    const float* temp_dct  = (const float*)d_in[6];
    float* out = (float*)d_out;

    float* B = nullptr; int* IB = nullptr; int* FC = nullptr;
    cudaGetSymbolAddress((void**)&B, g_buf);
    cudaGetSymbolAddress((void**)&IB, g_ibuf);
    cudaGetSymbolAddress((void**)&FC, g_fullCnt);

    float* P0 = B + O_P0;     float* P1 = B + O_P1;
    float* QN = B + O_QN;     float* G = B + O_G;
    float* L = B + O_L;       float* CERT = B + O_CERT;
    float* SELV = B + O_SELV;
    float* ABSR = B + O_STAT; float* ABSD = ABSR + NQ;
    float* RELR = ABSD + NQ;  float* RELD = RELR + NQ;
    float* SC1 = B + O_SC1;   float* SC2 = B + O_SC2;
    float* KL = B + O_KL;     float* PART = B + O_PART;
    int* RES = IB + IO_RES;   int* DCT = IB + IO_DCT;
    int* SELI = IB + IO_SELI; int* PSE = IB + IO_PSE;
    int* SELK = IB + IO_SELK; int* CNTS = IB + IO_CNTS;
    const int* CR = CNTS;     const int* CD = CNTS + 1;

    const float* Aq[2] = { x_query, dct_query };

    // -------- phase 1 --------
    JSet j1 = {};
    for (int s = 0; s < 2; s++) {
        j1.A[s] = Aq[s]; j1.qn[s] = QN + s*NQ;
        j1.P0[s] = P0 + s*SLP; j1.G[s] = G + (size_t)s*NQ*WAY;
        j1.map[s] = nullptr; j1.cnt[s] = FC;
        j1.P1[s] = P1 + s*SLP;
        j1.cert[s] = CERT + s*NQ; j1.selv[s] = SELV + s*KSEL;
        j1.sc1[s] = SC1 + s*WAY; j1.sc2[s] = SC2 + s*WAY;
        j1.seli[s] = SELI + s*KSEL; j1.selk[s] = SELK + s; j1.pse[s] = PSE + s*KSEL;
        j1.part[s] = PART + (size_t)s*NT*112;
    }
    k_proto0<<<dim3(WAY,2), 256>>>(x_shot, dct_shot, P0, P0 + SLP);
    k_qnorm<<<dim3(NQ,2), 256>>>(x_query, dct_query, QN, QN + NQ);

    GJobs g1 = {};
    for (int s = 0; s < 2; s++)
        g1.j[s] = { Aq[s], QN + s*NQ, P0 + s*SLP, G + (size_t)s*NQ*WAY,
                    PART + (size_t)s*NT*112, nullptr, FC };
    k_gemm<<<2*NT, 256>>>(g1);
    k_colreduce<<<2, 128>>>(j1, tp, 0, 0);
    k_cert<<<dim3((NQ+255)/256, 2), 256>>>(j1);
    k_topk<<<2, 1024>>>(j1);
    k_proto1<<<dim3(WAY,2), 256>>>(j1);

    GJobs g2 = {};
    for (int s = 0; s < 2; s++)
        g2.j[s] = { Aq[s], QN + s*NQ, P1 + s*SLP, L + (size_t)s*NQ*WAY,
                    PART + (size_t)s*NT*112, nullptr, FC };
    k_gemm<<<2*NT, 256>>>(g2);
    k_colreduce<<<2, 128>>>(j1, tp, 1, 0);

    RSJ rs;
    rs.L[0] = L; rs.L[1] = L + (size_t)NQ*WAY;
    rs.sc[0] = SC2; rs.sc[1] = SC2 + WAY;
    rs.absc[0] = ABSR; rs.absc[1] = ABSD;
    rs.relc[0] = RELR; rs.relc[1] = RELD;
    k_rowstats<<<dim3((NQ+7)/8, 2), 256>>>(rs);

    k_partition<<<1, 1024>>>(ABSR, ABSD, RELR, RELD, RES, DCT, CNTS, out);

    // -------- phase 3: jobs 0 x/RES  1 dct/RES  2 dct/DCT  3 x/DCT --------
    int src[4] = { 0, 1, 1, 0 };
    const int* mp[4] = { RES, RES, DCT, DCT };
    const int* cn[4] = { CR, CR, CD, CD };
    int slab[4] = { 0, 2, 3, 1 };
    JSet j3 = {};
    for (int s = 0; s < 4; s++) {
        int u = src[s];
        j3.A[s] = Aq[u]; j3.qn[s] = QN + u*NQ;
        j3.P0[s] = P0 + u*SLP; j3.G[s] = G + (size_t)u*NQ*WAY;
        j3.map[s] = mp[s]; j3.cnt[s] = cn[s];
        j3.P1[s] = P1 + s*SLP;
        j3.cert[s] = CERT + s*NQ; j3.selv[s] = SELV + s*KSEL;
        j3.sc1[s] = SC1 + s*WAY; j3.sc2[s] = SC2 + s*WAY;
        j3.seli[s] = SELI + s*KSEL; j3.selk[s] = SELK + s; j3.pse[s] = PSE + s*KSEL;
        j3.part[s] = PART + (size_t)slab[s]*NT*112;
    }
    k_subpart<<<dim3(NT,2), 128>>>(G, G + (size_t)NQ*WAY, ABSR, ABSD, RELR, RELD, PART);
    k_colreduce<<<4, 128>>>(j3, tp, 0, NT);
    k_cert<<<dim3((NQ+255)/256, 4), 256>>>(j3);
    k_topk<<<4, 1024>>>(j3);
    k_proto1<<<dim3(WAY,4), 256>>>(j3);

    JSet j3b = j3;
    for (int s = 0; s < 4; s++) j3b.part[s] = PART + (size_t)s*NT*112;
    GJobs g3 = {};
    for (int s = 0; s < 4; s++)
        g3.j[s] = { j3.A[s], j3.qn[s], P1 + s*SLP, L + (size_t)s*NQ*WAY,
                    PART + (size_t)s*NT*112, mp[s], cn[s] };
    k_gemm<<<4*NT, 256>>>(g3);
    k_colreduce<<<4, 128>>>(j3b, tp, 1, 0);

    KLJ kj;
    kj.Lh[0] = L;                     kj.sch[0] = SC2;
    kj.Ll[0] = L + (size_t)NQ*WAY;    kj.scl[0] = SC2 + WAY;
    kj.cnt[0] = CR; kj.kl[0] = KL;
    kj.Lh[1] = L + (size_t)2*NQ*WAY;  kj.sch[1] = SC2 + 2*WAY;
    kj.Ll[1] = L + (size_t)3*NQ*WAY;  kj.scl[1] = SC2 + 3*WAY;
    kj.cnt[1] = CD; kj.kl[1] = KL + WAY;
    k_classkl<<<dim3(WAY,2), 256>>>(kj);

    FinJ fj;
    fj.kl[0] = KL;       fj.absc[0] = ABSR; fj.idx[0] = RES; fj.cnt[0] = CR;
    fj.tsc[0] = temp_dct; fj.slot[0] = out + 1;
    fj.kl[1] = KL + WAY; fj.absc[1] = ABSD; fj.idx[1] = DCT; fj.cnt[1] = CD;
    fj.tsc[1] = temp;    fj.slot[1] = out + 0;
    k_finalize<<<2, 256>>>(fj);
}